// round 1
// baseline (speedup 1.0000x reference)
#include <cuda_runtime.h>
#include <math.h>

#define NBATCH 16
#define NP     4096
#define TOTAL  (NBATCH * NP)        // 65536 points per tensor
#define THREADS 256
#define TILES   (NP / THREADS)      // 16 query tiles per batch
#define NBLOCKS (2 * NBATCH * TILES) // 512 blocks (both directions)
#define SMEM_BYTES (NP * 16)        // 4096 float4 = 64 KB

// Scratch (no allocation allowed): packed points + per-block partial sums.
// g_pts[0 .. TOTAL)      = x packed as {px, py, pz, 0.5*|p|^2}
// g_pts[TOTAL .. 2TOTAL) = y packed
__device__ float4 g_pts[2 * TOTAL];
__device__ float  g_partial[NBLOCKS];

__global__ void pack_kernel(const float* __restrict__ x,
                            const float* __restrict__ y) {
    int i = blockIdx.x * blockDim.x + threadIdx.x;
    if (i >= 2 * TOTAL) return;
    const float* src = (i < TOTAL) ? x : y;
    int p = (i < TOTAL) ? i : (i - TOTAL);
    float a = src[3 * p + 0];
    float b = src[3 * p + 1];
    float c = src[3 * p + 2];
    g_pts[i] = make_float4(a, b, c, 0.5f * (a * a + b * b + c * c));
}

__global__ __launch_bounds__(THREADS) void chamfer_kernel() {
    extern __shared__ float4 sdb[];   // database tile: all 4096 points of one batch
    __shared__ float red[THREADS];

    int blk = blockIdx.x;
    int dir = (blk >= NBATCH * TILES) ? 1 : 0; // dir 0: query=x, db=y; dir 1: swapped
    int rem = blk - dir * (NBATCH * TILES);
    int b    = rem / TILES;
    int tile = rem % TILES;

    const float4* qp  = g_pts + (dir ? TOTAL : 0) + b * NP;
    const float4* dbp = g_pts + (dir ? 0 : TOTAL) + b * NP;

    int tid = threadIdx.x;

    // Cooperative coalesced load of the full database batch into shared.
    #pragma unroll
    for (int k = tid; k < NP; k += THREADS) sdb[k] = dbp[k];
    __syncthreads();

    float4 q = qp[tile * THREADS + tid];

    // min over j of t_j = 0.5*|s_j|^2 - q.s_j  (4 accumulators to break dep chain)
    float m0 = 1e30f, m1 = 1e30f, m2 = 1e30f, m3 = 1e30f;
    #pragma unroll 4
    for (int j = 0; j < NP; j += 4) {
        float4 s0 = sdb[j + 0];
        float4 s1 = sdb[j + 1];
        float4 s2 = sdb[j + 2];
        float4 s3 = sdb[j + 3];
        float t0 = fmaf(-q.x, s0.x, fmaf(-q.y, s0.y, fmaf(-q.z, s0.z, s0.w)));
        float t1 = fmaf(-q.x, s1.x, fmaf(-q.y, s1.y, fmaf(-q.z, s1.z, s1.w)));
        float t2 = fmaf(-q.x, s2.x, fmaf(-q.y, s2.y, fmaf(-q.z, s2.z, s2.w)));
        float t3 = fmaf(-q.x, s3.x, fmaf(-q.y, s3.y, fmaf(-q.z, s3.z, s3.w)));
        m0 = fminf(m0, t0);
        m1 = fminf(m1, t1);
        m2 = fminf(m2, t2);
        m3 = fminf(m3, t3);
    }
    float m = fminf(fminf(m0, m1), fminf(m2, m3));

    // ||q - s||^2 = 2*(0.5|q|^2 + m); clamp at 0; sqrt(eps + sq)
    float sq = fmaxf(2.0f * (q.w + m), 0.0f);
    float d  = sqrtf(1e-6f + sq);

    // Deterministic fixed-tree block reduction (no float atomics).
    red[tid] = d;
    __syncthreads();
    #pragma unroll
    for (int s = THREADS / 2; s > 0; s >>= 1) {
        if (tid < s) red[tid] += red[tid + s];
        __syncthreads();
    }
    if (tid == 0) g_partial[blk] = red[0];
}

__global__ void finalize_kernel(float* __restrict__ out) {
    __shared__ float red[NBLOCKS];
    int tid = threadIdx.x;
    red[tid] = g_partial[tid];
    __syncthreads();
    #pragma unroll
    for (int s = NBLOCKS / 2; s > 0; s >>= 1) {
        if (tid < s) red[tid] += red[tid + s];
        __syncthreads();
    }
    // mean(min1) + mean(min2) = (sum over both directions) / 65536
    if (tid == 0) out[0] = red[0] * (1.0f / (float)TOTAL);
}

extern "C" void kernel_launch(void* const* d_in, const int* in_sizes, int n_in,
                              void* d_out, int out_size) {
    const float* x = (const float*)d_in[0];
    const float* y = (const float*)d_in[1];
    float* out = (float*)d_out;

    cudaFuncSetAttribute(chamfer_kernel,
                         cudaFuncAttributeMaxDynamicSharedMemorySize, SMEM_BYTES);

    pack_kernel<<<(2 * TOTAL + 255) / 256, 256>>>(x, y);
    chamfer_kernel<<<NBLOCKS, THREADS, SMEM_BYTES>>>();
    finalize_kernel<<<1, NBLOCKS>>>(out);
}

// round 2
// speedup vs baseline: 1.5603x; 1.5603x over previous
#include <cuda_runtime.h>
#include <math.h>

#define NBATCH 16
#define NP     4096
#define TOTAL  (NBATCH * NP)          // 65536 points per tensor
#define THREADS 64
#define QPT     2                     // queries per thread
#define QBLK    (THREADS * QPT)       // 128 queries per block
#define NBLOCKS (2 * TOTAL / QBLK)    // 1024 blocks (both directions)
#define TILE_F4 1024                  // float4s per db tile (= 1024 points, 16KB)
#define TILE_PAIRS (TILE_F4 / 2)      // 512 packed db-point pairs per tile
#define NTILES  (NP / TILE_F4)        // 4 tiles cover the 4096-point db

// Scratch (no allocation allowed).
// g_q[p]      : per-point {x, y, z, 0.5*|p|^2}, x-tensor then y-tensor.
// g_pairs     : db-pair layout, 2 float4 per point pair:
//               [2k]   = {x0, x1, y0, y1}
//               [2k+1] = {z0, z1, w0, w1}   (w = 0.5*|p|^2)
__device__ float4 g_q[2 * TOTAL];
__device__ float4 g_pairs[2 * TOTAL];
__device__ float  g_partial[NBLOCKS];

// ---- Blackwell packed f32x2 helpers ----------------------------------------
#define FMA2(d, a, b, c) \
    asm("fma.rn.f32x2 %0, %1, %2, %3;" : "=l"(d) : "l"(a), "l"(b), "l"(c))

__device__ __forceinline__ unsigned long long bcast2(float v) {
    unsigned long long r;
    unsigned u = __float_as_uint(v);
    asm("mov.b64 %0, {%1, %1};" : "=l"(r) : "r"(u));
    return r;
}

__device__ __forceinline__ void minacc2(float& mlo, float& mhi,
                                        unsigned long long t) {
    unsigned lo, hi;
    asm("mov.b64 {%0, %1}, %2;" : "=r"(lo), "=r"(hi) : "l"(t));
    mlo = fminf(mlo, __uint_as_float(lo));
    mhi = fminf(mhi, __uint_as_float(hi));
}
// ----------------------------------------------------------------------------

__global__ void pack_kernel(const float* __restrict__ x,
                            const float* __restrict__ y) {
    int i = blockIdx.x * blockDim.x + threadIdx.x;  // global pair index
    if (i >= TOTAL) return;                         // 2*TOTAL points / 2
    int p0 = 2 * i;                                 // global point idx
    const float* src = (p0 < TOTAL) ? x : y;
    int l0 = (p0 < TOTAL) ? p0 : (p0 - TOTAL);

    // 6 consecutive floats, 24B-aligned -> three float2 loads
    const float2* s2 = (const float2*)(src + 3 * l0);
    float2 ab = s2[0];   // a0 b0
    float2 ca = s2[1];   // c0 a1
    float2 bc = s2[2];   // b1 c1

    float w0 = 0.5f * (ab.x * ab.x + ab.y * ab.y + ca.x * ca.x);
    float w1 = 0.5f * (ca.y * ca.y + bc.x * bc.x + bc.y * bc.y);

    g_q[p0]     = make_float4(ab.x, ab.y, ca.x, w0);
    g_q[p0 + 1] = make_float4(ca.y, bc.x, bc.y, w1);
    g_pairs[2 * i]     = make_float4(ab.x, ca.y, ab.y, bc.x);  // x0 x1 y0 y1
    g_pairs[2 * i + 1] = make_float4(ca.x, bc.y, w0, w1);      // z0 z1 w0 w1
}

__global__ __launch_bounds__(THREADS) void chamfer_kernel() {
    __shared__ float4 sdb[TILE_F4];   // 16 KB db tile
    __shared__ float  red[THREADS];

    int blk = blockIdx.x;
    int dir = blk >> 9;               // 512 blocks per direction
    int rem = blk & 511;
    int b     = rem >> 5;             // 32 blocks per batch
    int qtile = rem & 31;

    int tid = threadIdx.x;

    // dir 0: query = x tensor, db = y tensor; dir 1: swapped.
    int qOff  = dir ? TOTAL : 0;
    int dbOff = dir ? 0 : TOTAL;
    const float4* qp = g_q + qOff + b * NP + qtile * QBLK;

    float4 q0 = qp[tid];
    float4 q1 = qp[tid + THREADS];

    unsigned long long nqx0 = bcast2(-q0.x), nqy0 = bcast2(-q0.y), nqz0 = bcast2(-q0.z);
    unsigned long long nqx1 = bcast2(-q1.x), nqy1 = bcast2(-q1.y), nqz1 = bcast2(-q1.z);

    float m0lo = 1e30f, m0hi = 1e30f, m1lo = 1e30f, m1hi = 1e30f;

    const float4* dbBase = g_pairs + dbOff + b * NP;

    for (int t = 0; t < NTILES; ++t) {
        __syncthreads();
        const float4* src = dbBase + t * TILE_F4;
        #pragma unroll
        for (int k = tid; k < TILE_F4; k += THREADS) sdb[k] = src[k];
        __syncthreads();

        const ulonglong2* sp = (const ulonglong2*)sdb;
        #pragma unroll 8
        for (int j = 0; j < TILE_PAIRS; ++j) {
            ulonglong2 A = sp[2 * j];       // .x = {x0,x1}  .y = {y0,y1}
            ulonglong2 B = sp[2 * j + 1];   // .x = {z0,z1}  .y = {w0,w1}
            unsigned long long t0, t1;
            FMA2(t0, B.x, nqz0, B.y);
            FMA2(t0, A.y, nqy0, t0);
            FMA2(t0, A.x, nqx0, t0);
            FMA2(t1, B.x, nqz1, B.y);
            FMA2(t1, A.y, nqy1, t1);
            FMA2(t1, A.x, nqx1, t1);
            minacc2(m0lo, m0hi, t0);
            minacc2(m1lo, m1hi, t1);
        }
    }

    // t = 0.5|s|^2 - q.s ;  ||q-s||^2 = 2*(0.5|q|^2 + t)
    float m0 = fminf(m0lo, m0hi);
    float m1 = fminf(m1lo, m1hi);
    float d0 = sqrtf(1e-6f + fmaxf(2.0f * (q0.w + m0), 0.0f));
    float d1 = sqrtf(1e-6f + fmaxf(2.0f * (q1.w + m1), 0.0f));

    // Deterministic fixed-tree block reduction.
    red[tid] = d0 + d1;
    __syncthreads();
    #pragma unroll
    for (int s = THREADS / 2; s > 0; s >>= 1) {
        if (tid < s) red[tid] += red[tid + s];
        __syncthreads();
    }
    if (tid == 0) g_partial[blk] = red[0];
}

__global__ void finalize_kernel(float* __restrict__ out) {
    __shared__ float red[NBLOCKS];
    int tid = threadIdx.x;
    red[tid] = g_partial[tid];
    __syncthreads();
    #pragma unroll
    for (int s = NBLOCKS / 2; s > 0; s >>= 1) {
        if (tid < s) red[tid] += red[tid + s];
        __syncthreads();
    }
    if (tid == 0) out[0] = red[0] * (1.0f / (float)TOTAL);
}

extern "C" void kernel_launch(void* const* d_in, const int* in_sizes, int n_in,
                              void* d_out, int out_size) {
    const float* x = (const float*)d_in[0];
    const float* y = (const float*)d_in[1];
    float* out = (float*)d_out;

    pack_kernel<<<(TOTAL + 255) / 256, 256>>>(x, y);
    chamfer_kernel<<<NBLOCKS, THREADS>>>();
    finalize_kernel<<<1, NBLOCKS>>>(out);
}